// round 3
// baseline (speedup 1.0000x reference)
#include <cuda_runtime.h>

// Problem shape (fixed by reference)
#define Bdim  128
#define Tdim  1024
#define Idim  64
#define Hdim  512
#define BBdim 128
#define Odim  2

#define NCTA 128   // one CTA per 4 hidden units; also CTA j <-> batch j for phys/head
#define NTHR 256

// Cross-CTA state (persistent kernel; no allocations allowed)
__device__ float g_h[Bdim * Hdim];      // h_{t-1} / h_t
__device__ float g_hl[Bdim * Hdim];     // h_lstm at current step
__device__ float g_f[Bdim * BBdim];     // backbone activations
__device__ unsigned g_bar_count;
__device__ volatile unsigned g_bar_flag;

__device__ __forceinline__ float sigm(float v) { return 1.0f / (1.0f + expf(-v)); }

// Software grid barrier. 128 CTAs, 1 CTA/SM, single wave => safe.
// Sense value is read from the (persistent) flag at kernel start so graph
// replays work without any reset kernel.
__device__ __forceinline__ void grid_sync(unsigned &expect) {
    __syncthreads();
    if (threadIdx.x == 0) {
        expect += 1u;
        __threadfence();                         // release my phase's global writes
        if (atomicAdd(&g_bar_count, 1u) == NCTA - 1) {
            g_bar_count = 0;
            __threadfence();
            g_bar_flag = expect;
        } else {
            while (g_bar_flag != expect) { }
        }
    }
    __syncthreads();
}

__global__ __launch_bounds__(NTHR, 1)
void cfc_kernel(const float* __restrict__ x,
                const float* __restrict__ lstm_Wi, const float* __restrict__ lstm_bi,
                const float* __restrict__ lstm_Wh,
                const float* __restrict__ bb_W,  const float* __restrict__ bb_b,
                const float* __restrict__ ff1_W, const float* __restrict__ ff1_b,
                const float* __restrict__ ff2_W, const float* __restrict__ ff2_b,
                const float* __restrict__ ta_W,  const float* __restrict__ ta_b,
                const float* __restrict__ tb_W,  const float* __restrict__ tb_b,
                const float* __restrict__ head_W, const float* __restrict__ head_b,
                float* __restrict__ out)
{
    extern __shared__ float sm[];
    float* wA   = sm;                    // [16][576] gate rows (x-cols then h-cols)
    float* wB   = wA + 16 * 576;         // [16][576] bb_W row block
    float* wC   = wB + 16 * 576;         // [16][128] ff1/ff2/ta/tb rows (4 each)
    float* hW   = wC + 16 * 128;         // [2][512] head
    float* bA   = hW + 2 * 512;          // 16
    float* bB   = bA + 16;               // 16
    float* bC   = bB + 16;               // 16
    float* hb   = bC + 16;               // 16 (2 used)
    float* buf0 = hb + 16;               // [128][65] streaming tile (pad->no conflicts)
    float* buf1 = buf0 + 128 * 65;       // [128][65]

    const int tid  = threadIdx.x;
    const int j    = blockIdx.x;         // owns hidden units 4j..4j+3; batch j for head
    const int b    = tid & 127;          // batch lane for GEMM phases
    const int half = tid >> 7;           // k-split 0/1
    const int bb0  = (j >> 3) * 8;       // phase-B batch block
    const int jj0  = (j & 7) * 16;       // phase-B bb_W row block

    // ---- One-time: resident weights into smem ----
    for (int idx = tid; idx < 16 * 576; idx += NTHR) {
        int q = idx / 576, k = idx - q * 576;
        int grow = (q >> 2) * Hdim + 4 * j + (q & 3);   // gate g=q>>2, unit u=q&3
        wA[idx] = (k < Idim) ? lstm_Wi[grow * Idim + k]
                             : lstm_Wh[grow * Hdim + (k - Idim)];
    }
    for (int idx = tid; idx < 16 * 576; idx += NTHR) {
        int r = idx / 576, k = idx - r * 576;
        wB[idx] = bb_W[(jj0 + r) * 576 + k];
    }
    for (int idx = tid; idx < 16 * 128; idx += NTHR) {
        int r = idx >> 7, k = idx & 127;
        const float* Wm = (r < 4) ? ff1_W : (r < 8) ? ff2_W : (r < 12) ? ta_W : tb_W;
        wC[idx] = Wm[(4 * j + (r & 3)) * BBdim + k];
    }
    for (int idx = tid; idx < 2 * Hdim; idx += NTHR) hW[idx] = head_W[idx];
    if (tid < 16) {
        bA[tid] = lstm_bi[(tid >> 2) * Hdim + 4 * j + (tid & 3)];
        bB[tid] = bb_b[jj0 + tid];
        const float* bm = (tid < 4) ? ff1_b : (tid < 8) ? ff2_b : (tid < 12) ? ta_b : tb_b;
        bC[tid] = bm[4 * j + (tid & 3)];
    }
    if (tid < 2) hb[tid] = head_b[tid];
    __syncthreads();

    unsigned expect = 0;
    if (tid == 0) expect = g_bar_flag;   // safe: no flag writes before barrier 1 completes

    float cReg[4] = {0.f, 0.f, 0.f, 0.f};  // LSTM cell state, register-resident all T steps

    for (int t = 0; t < Tdim; ++t) {
        // ================= Phase A: z = [x_t,h] @ W.T, LSTM update =================
        float acc[16];
        #pragma unroll
        for (int q = 0; q < 16; q++) acc[q] = 0.f;

        const int NCH = (t == 0) ? 1 : 9;   // h=0 at t=0: only the x chunk

        {   // stage chunk 0 (x_t, all 128 batches, 64 cols) into buf0
            float4 st[8];
            #pragma unroll
            for (int r8 = 0; r8 < 8; r8++) {
                int idx4 = tid + NTHR * r8;
                int row = idx4 >> 4, c4 = idx4 & 15;
                st[r8] = *(const float4*)(x + (long)row * (Tdim * Idim) + t * Idim + c4 * 4);
            }
            #pragma unroll
            for (int r8 = 0; r8 < 8; r8++) {
                int idx4 = tid + NTHR * r8;
                int row = idx4 >> 4, c4 = idx4 & 15;
                float* d = buf0 + row * 65 + c4 * 4;
                d[0] = st[r8].x; d[1] = st[r8].y; d[2] = st[r8].z; d[3] = st[r8].w;
            }
        }
        __syncthreads();

        for (int c = 0; c < NCH; ++c) {
            float4 st[8];
            if (c + 1 < NCH) {               // prefetch next h chunk (cols c*64..)
                #pragma unroll
                for (int r8 = 0; r8 < 8; r8++) {
                    int idx4 = tid + NTHR * r8;
                    int row = idx4 >> 4, c4 = idx4 & 15;
                    st[r8] = __ldcg((const float4*)(g_h + row * Hdim + c * 64 + c4 * 4));
                }
            }
            const float* base = ((c & 1) ? buf1 : buf0) + b * 65;
            #pragma unroll
            for (int g4 = 0; g4 < 8; ++g4) {
                int kk = half * 32 + g4 * 4;
                float v0 = base[kk], v1 = base[kk + 1], v2 = base[kk + 2], v3 = base[kk + 3];
                const float* wp = wA + c * 64 + kk;
                #pragma unroll
                for (int q = 0; q < 16; q++) {
                    float4 w = *(const float4*)(wp + q * 576);
                    acc[q] = fmaf(v0, w.x, fmaf(v1, w.y, fmaf(v2, w.z, fmaf(v3, w.w, acc[q]))));
                }
            }
            if (c + 1 < NCH) {               // store prefetched chunk into other buffer
                float* nb = ((c + 1) & 1) ? buf1 : buf0;
                #pragma unroll
                for (int r8 = 0; r8 < 8; r8++) {
                    int idx4 = tid + NTHR * r8;
                    int row = idx4 >> 4, c4 = idx4 & 15;
                    float* d = nb + row * 65 + c4 * 4;
                    d[0] = st[r8].x; d[1] = st[r8].y; d[2] = st[r8].z; d[3] = st[r8].w;
                }
            }
            __syncthreads();
        }

        // pair-reduce the two k-halves (buf0 reused, stride 17 => conflict-free)
        if (half) {
            #pragma unroll
            for (int q = 0; q < 16; q++) buf0[b * 17 + q] = acc[q];
        }
        __syncthreads();
        if (!half) {
            float z[16];
            #pragma unroll
            for (int q = 0; q < 16; q++) z[q] = acc[q] + buf0[b * 17 + q] + bA[q];
            float hl[4];
            #pragma unroll
            for (int u = 0; u < 4; u++) {
                // z rows: [0..3]=i_, [4..7]=ig, [8..11]=fg, [12..15]=og
                float cn = cReg[u] * sigm(z[8 + u] + 1.0f) + tanhf(z[u]) * sigm(z[4 + u]);
                cReg[u] = cn;
                hl[u] = tanhf(cn) * sigm(z[12 + u]);
            }
            *(float4*)(g_hl + b * Hdim + 4 * j) = make_float4(hl[0], hl[1], hl[2], hl[3]);
        }

        // phys output for step t-1 (g_h still holds h_{t-1}); CTA j handles batch j
        if (t > 0 && tid < 64) {
            int o = tid >> 5, l = tid & 31;
            float s = 0.f;
            for (int n = l; n < Hdim; n += 32)
                s += __ldcg(g_h + j * Hdim + n) * hW[o * Hdim + n];
            #pragma unroll
            for (int off = 16; off; off >>= 1) s += __shfl_down_sync(0xffffffffu, s, off);
            if (l == 0) out[((long)j * Tdim + (t - 1)) * Odim + o] = s + hb[o];
        }
        grid_sync(expect);   // barrier 1: h_lstm complete

        // ================= Phase B: f = lecun_tanh([x_t,h_lstm] @ bbW.T + b) =======
        // CTA j computes f[bb0..bb0+7][jj0..jj0+15]
        for (int idx4 = tid; idx4 < 8 * 144; idx4 += NTHR) {
            int row = idx4 / 144, c4 = idx4 - row * 144;
            int col = c4 * 4;
            float4 v;
            if (col < Idim)
                v = *(const float4*)(x + (long)(bb0 + row) * (Tdim * Idim) + t * Idim + col);
            else
                v = __ldcg((const float4*)(g_hl + (bb0 + row) * Hdim + col - Idim));
            *(float4*)(buf0 + row * 576 + col) = v;
        }
        __syncthreads();
        {
            int lb = tid >> 5, l = tid & 31;   // warp = local batch
            float a[16];
            #pragma unroll
            for (int r = 0; r < 16; r++) a[r] = 0.f;
            const float* xr = buf0 + lb * 576;
            for (int it = 0; it < 18; ++it) {
                int kk = it * 32 + l;
                float v = xr[kk];
                #pragma unroll
                for (int r = 0; r < 16; r++) a[r] = fmaf(v, wB[r * 576 + kk], a[r]);
            }
            #pragma unroll
            for (int r = 0; r < 16; r++) {
                #pragma unroll
                for (int off = 16; off; off >>= 1)
                    a[r] += __shfl_down_sync(0xffffffffu, a[r], off);
            }
            if (l == 0) {
                #pragma unroll
                for (int r = 0; r < 16; r++) {
                    float v = a[r] + bB[r];
                    g_f[(bb0 + lb) * BBdim + jj0 + r] = 1.7159f * tanhf(0.666f * v);
                }
            }
        }
        grid_sync(expect);   // barrier 2: f complete

        // ================= Phase C: ff1/ff2/ta/tb, h_new ===========================
        #pragma unroll
        for (int r8 = 0; r8 < 16; ++r8) {     // stage full f (128x128) into buf0|buf1
            int idx4 = tid + NTHR * r8;       // 4096 float4
            int row = idx4 >> 5, c4 = idx4 & 31;
            float4 v = __ldcg((const float4*)(g_f + row * BBdim + c4 * 4));
            float* d = ((c4 < 16) ? buf0 : buf1) + row * 65 + (c4 & 15) * 4;
            d[0] = v.x; d[1] = v.y; d[2] = v.z; d[3] = v.w;
        }
        __syncthreads();
        float ac[16];
        #pragma unroll
        for (int r = 0; r < 16; r++) ac[r] = 0.f;
        {
            const float* base = (half ? buf1 : buf0) + b * 65;
            const float* wbase = wC + half * 64;
            #pragma unroll
            for (int g4 = 0; g4 < 16; ++g4) {
                int kk = g4 * 4;
                float v0 = base[kk], v1 = base[kk + 1], v2 = base[kk + 2], v3 = base[kk + 3];
                #pragma unroll
                for (int r = 0; r < 16; r++) {
                    float4 w = *(const float4*)(wbase + r * 128 + kk);
                    ac[r] = fmaf(v0, w.x, fmaf(v1, w.y, fmaf(v2, w.z, fmaf(v3, w.w, ac[r]))));
                }
            }
        }
        __syncthreads();
        if (half) {
            #pragma unroll
            for (int r = 0; r < 16; r++) buf0[b * 17 + r] = ac[r];
        }
        __syncthreads();
        if (!half) {
            float z[16];
            #pragma unroll
            for (int r = 0; r < 16; r++) z[r] = ac[r] + buf0[b * 17 + r] + bC[r];
            float hn[4];
            #pragma unroll
            for (int u = 0; u < 4; u++) {
                float f1 = tanhf(z[u]);          // ff1
                float f2 = tanhf(z[4 + u]);      // ff2
                float ti = sigm(z[8 + u] + z[12 + u]);   // sigmoid(ta*1 + tb)
                hn[u] = f1 * (1.f - ti) + ti * f2;
            }
            *(float4*)(g_h + b * Hdim + 4 * j) = make_float4(hn[0], hn[1], hn[2], hn[3]);
        }
        grid_sync(expect);   // barrier 3: h_t complete
    }

    // ---- Epilogue: phys for t = T-1, and last_h ----
    if (tid < 64) {
        int o = tid >> 5, l = tid & 31;
        float s = 0.f;
        for (int n = l; n < Hdim; n += 32)
            s += __ldcg(g_h + j * Hdim + n) * hW[o * Hdim + n];
        #pragma unroll
        for (int off = 16; off; off >>= 1) s += __shfl_down_sync(0xffffffffu, s, off);
        if (l == 0) out[((long)j * Tdim + (Tdim - 1)) * Odim + o] = s + hb[o];
    }
    float* out_lh = out + (long)Bdim * Tdim * Odim;
    for (int i4 = tid; i4 < Hdim / 4; i4 += NTHR) {
        float4 v = __ldcg((const float4*)(g_h + j * Hdim + i4 * 4));
        *(float4*)(out_lh + j * Hdim + i4 * 4) = v;
    }
}

extern "C" void kernel_launch(void* const* d_in, const int* in_sizes, int n_in,
                              void* d_out, int out_size) {
    (void)in_sizes; (void)n_in; (void)out_size;
    const int SMEM_BYTES = (16 * 576 + 16 * 576 + 16 * 128 + 2 * 512 + 64 + 2 * 128 * 65) * 4;
    cudaFuncSetAttribute(cfc_kernel, cudaFuncAttributeMaxDynamicSharedMemorySize, SMEM_BYTES);
    cfc_kernel<<<NCTA, NTHR, SMEM_BYTES>>>(
        (const float*)d_in[0],  (const float*)d_in[1],  (const float*)d_in[2],
        (const float*)d_in[3],  (const float*)d_in[4],  (const float*)d_in[5],
        (const float*)d_in[6],  (const float*)d_in[7],  (const float*)d_in[8],
        (const float*)d_in[9],  (const float*)d_in[10], (const float*)d_in[11],
        (const float*)d_in[12], (const float*)d_in[13], (const float*)d_in[14],
        (const float*)d_in[15], (float*)d_out);
}

// round 4
// speedup vs baseline: 1.0659x; 1.0659x over previous
#include <cuda_runtime.h>

// Problem shape (fixed by reference)
#define Bdim  128
#define Tdim  1024
#define Idim  64
#define Hdim  512
#define BBdim 128
#define Odim  2

#define NCTA 128   // one CTA per 4 hidden units; also CTA j <-> batch j for phys head
#define NTHR 512   // 16 warps -> 4 warps/SMSP for latency hiding

#define RS    68   // buffer row stride in floats (17 float4s, odd -> conflict-free)
#define PSTR  2176 // 128*17, partial-reduction block stride

// Cross-CTA state (persistent kernel; no allocations allowed)
__device__ float g_h[Bdim * Hdim];      // h_{t-1} / h_t
__device__ float g_hl[Bdim * Hdim];     // h_lstm at current step
__device__ float g_f[Bdim * BBdim];     // backbone activations
__device__ unsigned g_bar_count;
__device__ volatile unsigned g_bar_flag;

__device__ __forceinline__ float sigm(float v) { return 1.0f / (1.0f + expf(-v)); }

// Software grid barrier. 128 CTAs, 1 CTA/SM, single wave => safe.
// Sense value read from the persistent flag at kernel start so graph replays
// work without a reset kernel.
__device__ __forceinline__ void grid_sync(unsigned &expect) {
    __syncthreads();
    if (threadIdx.x == 0) {
        expect += 1u;
        __threadfence();                         // release my phase's global writes
        if (atomicAdd(&g_bar_count, 1u) == NCTA - 1) {
            g_bar_count = 0;
            __threadfence();
            g_bar_flag = expect;
        } else {
            while (g_bar_flag != expect) { }
        }
    }
    __syncthreads();
}

__global__ __launch_bounds__(NTHR, 1)
void cfc_kernel(const float* __restrict__ x,
                const float* __restrict__ lstm_Wi, const float* __restrict__ lstm_bi,
                const float* __restrict__ lstm_Wh,
                const float* __restrict__ bb_W,  const float* __restrict__ bb_b,
                const float* __restrict__ ff1_W, const float* __restrict__ ff1_b,
                const float* __restrict__ ff2_W, const float* __restrict__ ff2_b,
                const float* __restrict__ ta_W,  const float* __restrict__ ta_b,
                const float* __restrict__ tb_W,  const float* __restrict__ tb_b,
                const float* __restrict__ head_W, const float* __restrict__ head_b,
                float* __restrict__ out)
{
    extern __shared__ float sm[];
    float* wA   = sm;                    // [16][576] gate rows (x-cols then h-cols)
    float* wB   = wA + 16 * 576;         // [16][576] bb_W row block
    float* wC   = wB + 16 * 576;         // [16][128] ff1/ff2/ta/tb rows (4 each)
    float* hW   = wC + 16 * 128;         // [2][512] head
    float* bA   = hW + 2 * 512;          // 16
    float* bB   = bA + 16;               // 16
    float* bC   = bB + 16;               // 16
    float* hb   = bC + 16;               // 16 (2 used)
    float* buf0 = hb + 16;               // [128][RS] streaming tile
    float* buf1 = buf0 + 128 * RS;       // [128][RS]

    const int tid = threadIdx.x;
    const int j   = blockIdx.x;          // owns hidden units 4j..4j+3; batch j for head
    const int b   = tid & 127;           // batch lane for GEMM phases
    const int qtr = tid >> 7;            // k-split 0..3 (uniform per warp)
    const int bb0 = (j >> 3) * 8;        // phase-B batch block
    const int jj0 = (j & 7) * 16;        // phase-B bb_W row block

    // ---- One-time: resident weights into smem ----
    for (int idx = tid; idx < 16 * 576; idx += NTHR) {
        int q = idx / 576, k = idx - q * 576;
        int grow = (q >> 2) * Hdim + 4 * j + (q & 3);   // gate g=q>>2, unit u=q&3
        wA[idx] = (k < Idim) ? lstm_Wi[grow * Idim + k]
                             : lstm_Wh[grow * Hdim + (k - Idim)];
    }
    for (int idx = tid; idx < 16 * 576; idx += NTHR) {
        int r = idx / 576, k = idx - r * 576;
        wB[idx] = bb_W[(jj0 + r) * 576 + k];
    }
    for (int idx = tid; idx < 16 * 128; idx += NTHR) {
        int r = idx >> 7, k = idx & 127;
        const float* Wm = (r < 4) ? ff1_W : (r < 8) ? ff2_W : (r < 12) ? ta_W : tb_W;
        wC[idx] = Wm[(4 * j + (r & 3)) * BBdim + k];
    }
    for (int idx = tid; idx < 2 * Hdim; idx += NTHR) hW[idx] = head_W[idx];
    if (tid < 16) {
        bA[tid] = lstm_bi[(tid >> 2) * Hdim + 4 * j + (tid & 3)];
        bB[tid] = bb_b[jj0 + tid];
        const float* bm = (tid < 4) ? ff1_b : (tid < 8) ? ff2_b : (tid < 12) ? ta_b : tb_b;
        bC[tid] = bm[4 * j + (tid & 3)];
    }
    if (tid < 2) hb[tid] = head_b[tid];
    __syncthreads();

    unsigned expect = 0;
    if (tid == 0) expect = g_bar_flag;   // stable until all CTAs reach barrier 1

    float cReg[4] = {0.f, 0.f, 0.f, 0.f};  // LSTM cell state, register-resident

    for (int t = 0; t < Tdim; ++t) {
        // ============ Phase A: z = [x_t,h] @ W.T, LSTM update ============
        float acc[16];
        #pragma unroll
        for (int q = 0; q < 16; q++) acc[q] = 0.f;

        const int NCH = (t == 0) ? 1 : 9;   // h=0 at t=0: only the x chunk

        {   // stage chunk 0 (x_t: 128 batches x 64 cols) into buf0
            float4 st[4];
            #pragma unroll
            for (int r4 = 0; r4 < 4; r4++) {
                int idx4 = tid + NTHR * r4;
                int row = idx4 >> 4, c4 = idx4 & 15;
                st[r4] = *(const float4*)(x + (long)row * (Tdim * Idim) + t * Idim + c4 * 4);
            }
            #pragma unroll
            for (int r4 = 0; r4 < 4; r4++) {
                int idx4 = tid + NTHR * r4;
                int row = idx4 >> 4, c4 = idx4 & 15;
                *(float4*)(buf0 + row * RS + c4 * 4) = st[r4];
            }
        }
        __syncthreads();

        for (int c = 0; c < NCH; ++c) {
            float4 st[4];
            if (c + 1 < NCH) {               // prefetch next h chunk (h cols c*64..)
                #pragma unroll
                for (int r4 = 0; r4 < 4; r4++) {
                    int idx4 = tid + NTHR * r4;
                    int row = idx4 >> 4, c4 = idx4 & 15;
                    st[r4] = __ldcg((const float4*)(g_h + row * Hdim + c * 64 + c4 * 4));
                }
            }
            const float* base = ((c & 1) ? buf1 : buf0) + b * RS + qtr * 16;
            const float* wpc  = wA + c * 64 + qtr * 16;
            #pragma unroll
            for (int g4 = 0; g4 < 4; ++g4) {
                float4 av = *(const float4*)(base + g4 * 4);
                const float* wp = wpc + g4 * 4;
                #pragma unroll
                for (int q = 0; q < 16; q++) {
                    float4 w = *(const float4*)(wp + q * 576);
                    acc[q] = fmaf(av.x, w.x, fmaf(av.y, w.y,
                             fmaf(av.z, w.z, fmaf(av.w, w.w, acc[q]))));
                }
            }
            if (c + 1 < NCH) {
                float* nb = ((c + 1) & 1) ? buf1 : buf0;
                #pragma unroll
                for (int r4 = 0; r4 < 4; r4++) {
                    int idx4 = tid + NTHR * r4;
                    int row = idx4 >> 4, c4 = idx4 & 15;
                    *(float4*)(nb + row * RS + c4 * 4) = st[r4];
                }
            }
            __syncthreads();
        }

        // 4-way k-partial reduction (stride-17 => conflict-free)
        if (qtr) {
            #pragma unroll
            for (int q = 0; q < 16; q++) buf0[(qtr - 1) * PSTR + b * 17 + q] = acc[q];
        }
        __syncthreads();
        if (!qtr) {
            float z[16];
            #pragma unroll
            for (int q = 0; q < 16; q++)
                z[q] = acc[q] + buf0[b * 17 + q] + buf0[PSTR + b * 17 + q]
                     + buf0[2 * PSTR + b * 17 + q] + bA[q];
            float hl[4];
            #pragma unroll
            for (int u = 0; u < 4; u++) {
                // z rows: [0..3]=i_, [4..7]=ig, [8..11]=fg, [12..15]=og
                float cn = cReg[u] * sigm(z[8 + u] + 1.0f) + tanhf(z[u]) * sigm(z[4 + u]);
                cReg[u] = cn;
                hl[u] = tanhf(cn) * sigm(z[12 + u]);
            }
            *(float4*)(g_hl + b * Hdim + 4 * j) = make_float4(hl[0], hl[1], hl[2], hl[3]);
        }

        // phys output for step t-1 (g_h still holds h_{t-1}); CTA j handles batch j
        if (t > 0 && tid < 64) {
            int o = tid >> 5, l = tid & 31;
            float s = 0.f;
            for (int n = l; n < Hdim; n += 32)
                s += __ldcg(g_h + j * Hdim + n) * hW[o * Hdim + n];
            #pragma unroll
            for (int off = 16; off; off >>= 1) s += __shfl_down_sync(0xffffffffu, s, off);
            if (l == 0) out[((long)j * Tdim + (t - 1)) * Odim + o] = s + hb[o];
        }
        grid_sync(expect);   // barrier 1: h_lstm complete

        // ============ Phase B: f = lecun_tanh([x_t,h_lstm] @ bbW.T + b) ============
        // CTA j computes f[bb0..bb0+7][jj0..jj0+15]; warp = (local batch, k-half)
        for (int idx4 = tid; idx4 < 8 * 144; idx4 += NTHR) {
            int row = idx4 / 144, c4 = idx4 - row * 144;
            int col = c4 * 4;
            float4 v;
            if (col < Idim)
                v = *(const float4*)(x + (long)(bb0 + row) * (Tdim * Idim) + t * Idim + col);
            else
                v = __ldcg((const float4*)(g_hl + (bb0 + row) * Hdim + col - Idim));
            *(float4*)(buf0 + row * 576 + col) = v;
        }
        __syncthreads();
        {
            int w  = tid >> 5, l = tid & 31;
            int lb = w >> 1, kh = w & 1;     // local batch 0..7, k-half 0/1
            float a[16];
            #pragma unroll
            for (int r = 0; r < 16; r++) a[r] = 0.f;
            const float* xr = buf0 + lb * 576 + kh * 288;
            const float* wb = wB + kh * 288;
            for (int it = 0; it < 9; ++it) {
                int kk = it * 32 + l;
                float v = xr[kk];
                #pragma unroll
                for (int r = 0; r < 16; r++) a[r] = fmaf(v, wb[r * 576 + kk], a[r]);
            }
            #pragma unroll
            for (int r = 0; r < 16; r++) {
                #pragma unroll
                for (int off = 16; off; off >>= 1)
                    a[r] += __shfl_down_sync(0xffffffffu, a[r], off);
            }
            if (l == 0) {
                #pragma unroll
                for (int r = 0; r < 16; r++) buf1[(lb * 2 + kh) * 16 + r] = a[r];
            }
        }
        __syncthreads();
        if (tid < 128) {    // distribute the tanh epilogue over 128 threads
            int lb = tid >> 4, r = tid & 15;
            float v = buf1[lb * 32 + r] + buf1[lb * 32 + 16 + r] + bB[r];
            g_f[(bb0 + lb) * BBdim + jj0 + r] = 1.7159f * tanhf(0.666f * v);
        }
        grid_sync(expect);   // barrier 2: f complete

        // ============ Phase C: ff1/ff2/ta/tb, h_new ============
        #pragma unroll
        for (int r8 = 0; r8 < 8; ++r8) {     // stage full f (128x128) into buf0|buf1
            int idx4 = tid + NTHR * r8;      // 4096 float4
            int row = idx4 >> 5, c4 = idx4 & 31;
            float4 v = __ldcg((const float4*)(g_f + row * BBdim + c4 * 4));
            *(float4*)(((c4 < 16) ? buf0 : buf1) + row * RS + (c4 & 15) * 4) = v;
        }
        __syncthreads();
        float ac[16];
        #pragma unroll
        for (int r = 0; r < 16; r++) ac[r] = 0.f;
        {
            const float* base = ((qtr >= 2) ? buf1 : buf0) + b * RS + (qtr & 1) * 32;
            const float* wpc  = wC + qtr * 32;
            #pragma unroll
            for (int g4 = 0; g4 < 8; ++g4) {
                float4 av = *(const float4*)(base + g4 * 4);
                const float* wp = wpc + g4 * 4;
                #pragma unroll
                for (int r = 0; r < 16; r++) {
                    float4 w = *(const float4*)(wp + r * 128);
                    ac[r] = fmaf(av.x, w.x, fmaf(av.y, w.y,
                            fmaf(av.z, w.z, fmaf(av.w, w.w, ac[r]))));
                }
            }
        }
        __syncthreads();
        if (qtr) {
            #pragma unroll
            for (int r = 0; r < 16; r++) buf0[(qtr - 1) * PSTR + b * 17 + r] = ac[r];
        }
        __syncthreads();
        if (!qtr) {
            float z[16];
            #pragma unroll
            for (int r = 0; r < 16; r++)
                z[r] = ac[r] + buf0[b * 17 + r] + buf0[PSTR + b * 17 + r]
                     + buf0[2 * PSTR + b * 17 + r] + bC[r];
            float hn[4];
            #pragma unroll
            for (int u = 0; u < 4; u++) {
                float f1 = tanhf(z[u]);                  // ff1
                float f2 = tanhf(z[4 + u]);              // ff2
                float ti = sigm(z[8 + u] + z[12 + u]);   // sigmoid(ta*1 + tb)
                hn[u] = f1 * (1.f - ti) + ti * f2;
            }
            *(float4*)(g_h + b * Hdim + 4 * j) = make_float4(hn[0], hn[1], hn[2], hn[3]);
        }
        grid_sync(expect);   // barrier 3: h_t complete
    }

    // ---- Epilogue: phys for t = T-1, and last_h ----
    if (tid < 64) {
        int o = tid >> 5, l = tid & 31;
        float s = 0.f;
        for (int n = l; n < Hdim; n += 32)
            s += __ldcg(g_h + j * Hdim + n) * hW[o * Hdim + n];
        #pragma unroll
        for (int off = 16; off; off >>= 1) s += __shfl_down_sync(0xffffffffu, s, off);
        if (l == 0) out[((long)j * Tdim + (Tdim - 1)) * Odim + o] = s + hb[o];
    }
    float* out_lh = out + (long)Bdim * Tdim * Odim;
    for (int i4 = tid; i4 < Hdim / 4; i4 += NTHR) {
        float4 v = __ldcg((const float4*)(g_h + j * Hdim + i4 * 4));
        *(float4*)(out_lh + j * Hdim + i4 * 4) = v;
    }
}

extern "C" void kernel_launch(void* const* d_in, const int* in_sizes, int n_in,
                              void* d_out, int out_size) {
    (void)in_sizes; (void)n_in; (void)out_size;
    const int SMEM_BYTES = (16 * 576 + 16 * 576 + 16 * 128 + 2 * 512 + 64
                            + 2 * 128 * RS) * 4;
    cudaFuncSetAttribute(cfc_kernel, cudaFuncAttributeMaxDynamicSharedMemorySize, SMEM_BYTES);
    cfc_kernel<<<NCTA, NTHR, SMEM_BYTES>>>(
        (const float*)d_in[0],  (const float*)d_in[1],  (const float*)d_in[2],
        (const float*)d_in[3],  (const float*)d_in[4],  (const float*)d_in[5],
        (const float*)d_in[6],  (const float*)d_in[7],  (const float*)d_in[8],
        (const float*)d_in[9],  (const float*)d_in[10], (const float*)d_in[11],
        (const float*)d_in[12], (const float*)d_in[13], (const float*)d_in[14],
        (const float*)d_in[15], (float*)d_out);
}